// round 6
// baseline (speedup 1.0000x reference)
#include <cuda_runtime.h>
#include <math.h>

// OptNet_2525440770614 — register warp QP, Gauss-Jordan on [Q | -p, g].
//
// R5 post-mortem: halving the math chain changed nothing -> kernel window is
// dominated by fixed launch overhead (~T_ovh 5k cyc) + cold loads. This round
// trims the remaining addressable tail:
//  - viol = g.(zu - z0) - s0  (folds h into the final butterfly; deletes the
//    early 4-shuffle reduction block)
//  - no post-butterfly broadcasts (lanes 0-15 already uniform after 8..1)
//  - raw rcp.approx.f32 (MUFU only, no NR fixup) on the GJ pivot chain

#define NC 10
#define QP_EPS 1e-4f
#define FULL 0xffffffffu

__device__ __forceinline__ float rcp_approx(float x) {
    float r;
    asm("rcp.approx.f32 %0, %1;" : "=f"(r) : "f"(x));
    return r;
}

__global__ void __launch_bounds__(32, 1)
optnet_qp_gj2(const float* __restrict__ L,
              const float* __restrict__ p,
              const float* __restrict__ G,
              const float* __restrict__ z0,
              const float* __restrict__ s0,
              float* __restrict__ out) {
    const int lane = threadIdx.x;
    const bool act = (lane < NC);

    // ---- front-batched independent loads ----
    float l[NC];                        // my tril row of L
    #pragma unroll
    for (int k = 0; k < NC; k++)
        l[k] = (act && k <= lane) ? L[lane * NC + k] : 0.0f;

    float gv  = act ? G[lane]  : 0.0f;
    float z0v = act ? z0[lane] : 0.0f;
    float pv  = act ? p[lane]  : 0.0f;
    float s0v = s0[0];

    // ---- Q row i: q[j] = sum_{k<=j} l_i[k] * l_j[k]  (+eps on diag) ----
    float q[NC];
    #pragma unroll
    for (int j = 0; j < NC; j++) {
        float s = (j == lane) ? QP_EPS : 0.0f;
        #pragma unroll
        for (int k = 0; k <= j; k++)
            s = fmaf(l[k], __shfl_sync(FULL, l[k], j), s);
        q[j] = s;
    }

    // ---- Gauss-Jordan on [Q | r1=-p, r2=g], no pivoting (SPD) ----
    float r1 = -pv, r2 = gv;
    float myrcp = 1.0f;

    #pragma unroll
    for (int j = 0; j < NC; j++) {
        float rs_local = rcp_approx(q[j]);         // MUFU only
        if (lane == j) myrcp = rs_local;
        float rs = __shfl_sync(FULL, rs_local, j); // pivot reciprocal
        float m  = q[j] * rs;                      // multiplier
        bool upd = (lane != j);
        #pragma unroll
        for (int k = j + 1; k < NC; k++) {
            float qjk = __shfl_sync(FULL, q[k], j);
            if (upd) q[k] = fmaf(-m, qjk, q[k]);
        }
        float rj1 = __shfl_sync(FULL, r1, j);
        float rj2 = __shfl_sync(FULL, r2, j);
        if (upd) {
            r1 = fmaf(-m, rj1, r1);
            r2 = fmaf(-m, rj2, r2);
        }
    }

    // ---- solutions ----
    float zu = act ? r1 * myrcp : 0.0f;   // Q^-1 (-p)
    float qg = act ? r2 * myrcp : 0.0f;   // Q^-1 g

    // ---- viol = g.(zu - z0) - s0 ; denom = g.qg  (overlapped butterflies,
    //      lanes 0-15 uniform afterwards; no broadcast needed) ----
    float da = gv * (zu - z0v);
    float db = gv * qg;
    #pragma unroll
    for (int o = 8; o >= 1; o >>= 1) {
        da += __shfl_xor_sync(FULL, da, o);
        db += __shfl_xor_sync(FULL, db, o);
    }
    float lam = __fdividef(fmaxf(da - s0v, 0.0f), db);

    // ---- z, log_softmax (fast MUFU; butterflies uniform over lanes 0-15) ----
    float zf = act ? fmaf(-lam, qg, zu) : -INFINITY;

    float mx = zf;
    #pragma unroll
    for (int o = 8; o >= 1; o >>= 1)
        mx = fmaxf(mx, __shfl_xor_sync(FULL, mx, o));

    float e = act ? __expf(zf - mx) : 0.0f;
    float se = e;
    #pragma unroll
    for (int o = 8; o >= 1; o >>= 1) se += __shfl_xor_sync(FULL, se, o);
    float lse = __logf(se);

    if (act) out[lane] = zf - mx - lse;
}

extern "C" void kernel_launch(void* const* d_in, const int* in_sizes, int n_in,
                              void* d_out, int out_size) {
    // metadata order: x, W1, b1, L, p, G, z0, s0
    const float* L  = (const float*)d_in[3];
    const float* p  = (const float*)d_in[4];
    const float* G  = (const float*)d_in[5];
    const float* z0 = (const float*)d_in[6];
    const float* s0 = (const float*)d_in[7];
    float* out = (float*)d_out;
    (void)in_sizes; (void)n_in; (void)out_size;

    optnet_qp_gj2<<<1, 32>>>(L, p, G, z0, s0, out);
}

// round 7
// speedup vs baseline: 1.0859x; 1.0859x over previous
#include <cuda_runtime.h>
#include <math.h>

// OptNet_2525440770614 — register warp QP, Gauss-Jordan on [Q | -p, g].
//
// R6 post-mortem: kernel 5.12->4.70us but dur_us moved opposite (noise
// +-0.4us dominates). Kernel is at the single-launch floor: ~1.2k cyc of
// dependent math + ~0.5k cold-load + fixed launch ramp. Final micro-trims:
//  - RHS shuffles hoisted above the k-loop in each GJ step (indep of m)
//  - raw ex2/lg2 softmax (no __expf mul / __logf fixup)
//  - rcp.approx.f32 pivots, viol folded as g.(zu-z0)-s0

#define NC 10
#define QP_EPS 1e-4f
#define FULL 0xffffffffu
#define LOG2E 1.4426950408889634f

__device__ __forceinline__ float rcp_approx(float x) {
    float r;
    asm("rcp.approx.f32 %0, %1;" : "=f"(r) : "f"(x));
    return r;
}
__device__ __forceinline__ float ex2_approx(float x) {
    float r;
    asm("ex2.approx.f32 %0, %1;" : "=f"(r) : "f"(x));
    return r;
}
__device__ __forceinline__ float lg2_approx(float x) {
    float r;
    asm("lg2.approx.f32 %0, %1;" : "=f"(r) : "f"(x));
    return r;
}

__global__ void __launch_bounds__(32, 1)
optnet_qp_gj3(const float* __restrict__ L,
              const float* __restrict__ p,
              const float* __restrict__ G,
              const float* __restrict__ z0,
              const float* __restrict__ s0,
              float* __restrict__ out) {
    const int lane = threadIdx.x;
    const bool act = (lane < NC);

    // ---- front-batched independent loads ----
    float l[NC];                        // my tril row of L
    #pragma unroll
    for (int k = 0; k < NC; k++)
        l[k] = (act && k <= lane) ? L[lane * NC + k] : 0.0f;

    float gv  = act ? G[lane]  : 0.0f;
    float z0v = act ? z0[lane] : 0.0f;
    float pv  = act ? p[lane]  : 0.0f;
    float s0v = s0[0];

    // ---- Q row i: q[j] = sum_{k<=j} l_i[k] * l_j[k]  (+eps on diag) ----
    float q[NC];
    #pragma unroll
    for (int j = 0; j < NC; j++) {
        float s = (j == lane) ? QP_EPS : 0.0f;
        #pragma unroll
        for (int k = 0; k <= j; k++)
            s = fmaf(l[k], __shfl_sync(FULL, l[k], j), s);
        q[j] = s;
    }

    // ---- Gauss-Jordan on [Q | r1=-p, r2=g], no pivoting (SPD) ----
    float r1 = -pv, r2 = gv;
    float myrcp = 1.0f;

    #pragma unroll
    for (int j = 0; j < NC; j++) {
        // RHS row-j values: depend only on previous iter -> issue first
        float rj1 = __shfl_sync(FULL, r1, j);
        float rj2 = __shfl_sync(FULL, r2, j);
        float rs_local = rcp_approx(q[j]);         // MUFU only
        if (lane == j) myrcp = rs_local;
        float rs = __shfl_sync(FULL, rs_local, j); // pivot reciprocal
        float m  = q[j] * rs;                      // multiplier
        bool upd = (lane != j);
        if (upd) {
            r1 = fmaf(-m, rj1, r1);
            r2 = fmaf(-m, rj2, r2);
        }
        #pragma unroll
        for (int k = j + 1; k < NC; k++) {
            float qjk = __shfl_sync(FULL, q[k], j);
            if (upd) q[k] = fmaf(-m, qjk, q[k]);
        }
    }

    // ---- solutions (mask: lanes >=10 hold NaN/inf garbage) ----
    float zu = act ? r1 * myrcp : 0.0f;   // Q^-1 (-p)
    float qg = act ? r2 * myrcp : 0.0f;   // Q^-1 g

    // ---- viol = g.(zu - z0) - s0 ; denom = g.qg (overlapped butterflies,
    //      results uniform across lanes 0-15, no broadcast needed) ----
    float da = gv * (zu - z0v);
    float db = gv * qg;
    #pragma unroll
    for (int o = 8; o >= 1; o >>= 1) {
        da += __shfl_xor_sync(FULL, da, o);
        db += __shfl_xor_sync(FULL, db, o);
    }
    float lam = __fdividef(fmaxf(da - s0v, 0.0f), db);

    // ---- z, log_softmax in log2 domain (raw MUFU ex2/lg2) ----
    float zf = act ? fmaf(-lam, qg, zu) : -INFINITY;

    float mx = zf;
    #pragma unroll
    for (int o = 8; o >= 1; o >>= 1)
        mx = fmaxf(mx, __shfl_xor_sync(FULL, mx, o));

    float t  = (zf - mx) * LOG2E;              // log2-domain exponent
    float e  = act ? ex2_approx(t) : 0.0f;
    float se = e;
    #pragma unroll
    for (int o = 8; o >= 1; o >>= 1) se += __shfl_xor_sync(FULL, se, o);
    float lse = lg2_approx(se) * (1.0f / LOG2E);   // back to natural log

    if (act) out[lane] = zf - mx - lse;
}

extern "C" void kernel_launch(void* const* d_in, const int* in_sizes, int n_in,
                              void* d_out, int out_size) {
    // metadata order: x, W1, b1, L, p, G, z0, s0
    const float* L  = (const float*)d_in[3];
    const float* p  = (const float*)d_in[4];
    const float* G  = (const float*)d_in[5];
    const float* z0 = (const float*)d_in[6];
    const float* s0 = (const float*)d_in[7];
    float* out = (float*)d_out;
    (void)in_sizes; (void)n_in; (void)out_size;

    optnet_qp_gj3<<<1, 32>>>(L, p, G, z0, s0, out);
}